// round 1
// baseline (speedup 1.0000x reference)
#include <cuda_runtime.h>
#include <cuda_bf16.h>

#define NB 8
#define PP 256
#define CC 128
#define US 132   // padded U row stride (floats) to kill smem bank conflicts

// Scratch (device globals; no allocation allowed)
__device__ __align__(16) float g_M[CC*CC];     // Wp2 @ W1
__device__ __align__(16) float g_Wq1[CC*CC];   // Wq @ W1
__device__ __align__(16) float g_Wk1[CC*CC];   // Wk @ W1
__device__ __align__(16) float g_c0[CC];       // b1 + bp2 @ W1
__device__ __align__(16) float g_v[NB*PP*CC];
__device__ __align__(16) float g_qW1[NB*PP*CC];
__device__ __align__(16) float g_kW1[NB*PP*CC];

// ---------------------------------------------------------------------------
// Kernel 1: tiny 128x128x128 weight-fold GEMMs  (M, Wq1, Wk1, c0)
// ---------------------------------------------------------------------------
__global__ void prep_weights(const float* __restrict__ Wq, const float* __restrict__ Wk,
                             const float* __restrict__ Wp2, const float* __restrict__ W1,
                             const float* __restrict__ b1, const float* __restrict__ bp2) {
    const float* A = (blockIdx.x == 0) ? Wp2 : ((blockIdx.x == 1) ? Wq : Wk);
    float* O       = (blockIdx.x == 0) ? g_M : ((blockIdx.x == 1) ? g_Wq1 : g_Wk1);
    for (int idx = threadIdx.x; idx < CC*CC; idx += blockDim.x) {
        int r = idx >> 7, d = idx & 127;
        float s0 = 0.f, s1 = 0.f, s2 = 0.f, s3 = 0.f;
        #pragma unroll 4
        for (int e = 0; e < CC; e += 4) {
            s0 += A[r*CC + e    ] * W1[(e    )*CC + d];
            s1 += A[r*CC + e + 1] * W1[(e + 1)*CC + d];
            s2 += A[r*CC + e + 2] * W1[(e + 2)*CC + d];
            s3 += A[r*CC + e + 3] * W1[(e + 3)*CC + d];
        }
        O[idx] = (s0 + s1) + (s2 + s3);
    }
    if (blockIdx.x == 0) {
        for (int d = threadIdx.x; d < CC; d += blockDim.x) {
            float s = b1[d];
            for (int e = 0; e < CC; e++) s += bp2[e] * W1[e*CC + d];
            g_c0[d] = s;
        }
    }
}

// ---------------------------------------------------------------------------
// Kernel 2: x projections  v = x@Wv, qW1 = x@Wq1, kW1 = x@Wk1
// grid (32, 3): blockIdx.x = 64-row slice of the 2048 rows, blockIdx.y = which
// ---------------------------------------------------------------------------
__global__ __launch_bounds__(256, 2)
void proj_kernel(const float* __restrict__ x, const float* __restrict__ Wv) {
    extern __shared__ float sm[];
    float* Wsh = sm;            // [128][128]
    float* Xsh = sm + CC*CC;    // [64][US]

    int which = blockIdx.y;
    const float* W = (which == 0) ? Wv   : ((which == 1) ? g_Wq1 : g_Wk1);
    float*       O = (which == 0) ? g_v  : ((which == 1) ? g_qW1 : g_kW1);
    int row0 = blockIdx.x * 64;
    int tid = threadIdx.x;

    for (int i = tid; i < CC*CC/4; i += 256)
        ((float4*)Wsh)[i] = ((const float4*)W)[i];
    for (int i = tid; i < 64*CC; i += 256) {
        int r = i >> 7, c = i & 127;
        Xsh[r*US + c] = x[(row0 + r)*CC + c];
    }
    __syncthreads();

    int tx = tid & 15, ty = tid >> 4;
    float acc[4][8];
    #pragma unroll
    for (int i = 0; i < 4; i++)
        #pragma unroll
        for (int j = 0; j < 8; j++) acc[i][j] = 0.f;

    #pragma unroll 4
    for (int c = 0; c < CC; c++) {
        float4 m0 = *(const float4*)&Wsh[c*CC + (tx << 3)];
        float4 m1 = *(const float4*)&Wsh[c*CC + (tx << 3) + 4];
        float m[8] = {m0.x, m0.y, m0.z, m0.w, m1.x, m1.y, m1.z, m1.w};
        float u[4];
        #pragma unroll
        for (int i = 0; i < 4; i++) u[i] = Xsh[(ty*4 + i)*US + c];
        #pragma unroll
        for (int i = 0; i < 4; i++)
            #pragma unroll
            for (int j = 0; j < 8; j++) acc[i][j] += u[i] * m[j];
    }

    #pragma unroll
    for (int i = 0; i < 4; i++) {
        float4* o4 = (float4*)&O[(row0 + ty*4 + i)*CC + (tx << 3)];
        o4[0] = make_float4(acc[i][0], acc[i][1], acc[i][2], acc[i][3]);
        o4[1] = make_float4(acc[i][4], acc[i][5], acc[i][6], acc[i][7]);
    }
}

// ---------------------------------------------------------------------------
// Kernel 3: fully fused main kernel. One block per (n, a) pair.
//   U = relu(pos@Wp1+bp1) built on the fly (2 FMA/elem),
//   G = U @ M (M resident in smem),
//   logit = relu(G + qW1[n,b] - kW1[n,a] + c0) . W2,
//   softmax over b (all 256 in-block), out = x + att@v.
// ---------------------------------------------------------------------------
__global__ __launch_bounds__(256, 2)
void main_kernel(const float* __restrict__ x, const float* __restrict__ pos,
                 const float* __restrict__ W2, const float* __restrict__ Wp1,
                 const float* __restrict__ bp1, float* __restrict__ out) {
    extern __shared__ float sm[];
    float* Msh    = sm;                 // 16384
    float* Ush    = Msh + CC*CC;        // 64*US = 8448
    float* kW1sh  = Ush + 64*US;        // 128
    float* c0sh   = kW1sh + CC;         // 128
    float* W2sh   = c0sh + CC;          // 128
    float* wpa    = W2sh + CC;          // 128
    float* wpb    = wpa + CC;           // 128
    float* bpsh   = wpb + CC;           // 128
    float* logits = bpsh + CC;          // 256
    float* red    = logits + PP;        // 256

    int blk = blockIdx.x;
    int n = blk >> 8;      // / 256
    int a = blk & 255;
    int tid = threadIdx.x;

    for (int i = tid; i < CC*CC/4; i += 256)
        ((float4*)Msh)[i] = ((const float4*)g_M)[i];
    if (tid < CC) {
        kW1sh[tid] = g_kW1[(n*PP + a)*CC + tid];
        c0sh[tid]  = g_c0[tid];
        W2sh[tid]  = W2[tid];
        wpa[tid]   = Wp1[tid];
        wpb[tid]   = Wp1[CC + tid];
        bpsh[tid]  = bp1[tid];
    }
    __syncthreads();

    int tx = tid & 15, ty = tid >> 4;

    for (int bc = 0; bc < 4; bc++) {
        int b0 = bc * 64;
        // stage pos for this 64-row chunk: red[2r], red[2r+1]
        if (tid < 128)
            red[tid] = pos[(((n*PP + a)*PP) + b0 + (tid >> 1))*2 + (tid & 1)];
        __syncthreads();

        // build U = relu(pos @ Wp1 + bp1)
        for (int i = tid; i < 64*CC; i += 256) {
            int r = i >> 7, c = i & 127;
            float uv = red[r*2] * wpa[c] + red[r*2 + 1] * wpb[c] + bpsh[c];
            Ush[r*US + c] = fmaxf(uv, 0.f);
        }
        __syncthreads();

        // G = U @ M, 4x8 register tile per thread over a 64x128 output chunk
        float acc[4][8];
        #pragma unroll
        for (int i = 0; i < 4; i++)
            #pragma unroll
            for (int j = 0; j < 8; j++) acc[i][j] = 0.f;

        #pragma unroll 4
        for (int c = 0; c < CC; c++) {
            float4 m0 = *(const float4*)&Msh[c*CC + (tx << 3)];
            float4 m1 = *(const float4*)&Msh[c*CC + (tx << 3) + 4];
            float m[8] = {m0.x, m0.y, m0.z, m0.w, m1.x, m1.y, m1.z, m1.w};
            float u[4];
            #pragma unroll
            for (int i = 0; i < 4; i++) u[i] = Ush[(ty*4 + i)*US + c];
            #pragma unroll
            for (int i = 0; i < 4; i++)
                #pragma unroll
                for (int j = 0; j < 8; j++) acc[i][j] += u[i] * m[j];
        }

        // fused epilogue: + qW1[n,b] - kW1[n,a] + c0, relu, dot W2
        #pragma unroll
        for (int i = 0; i < 4; i++) {
            int b = b0 + ty*4 + i;
            const float4* q4 = (const float4*)&g_qW1[(n*PP + b)*CC + (tx << 3)];
            float4 q0 = q4[0], q1 = q4[1];
            float qv[8] = {q0.x, q0.y, q0.z, q0.w, q1.x, q1.y, q1.z, q1.w};
            float pl = 0.f;
            int col = tx << 3;
            #pragma unroll
            for (int j = 0; j < 8; j++) {
                float h = acc[i][j] + qv[j] - kW1sh[col + j] + c0sh[col + j];
                pl += fmaxf(h, 0.f) * W2sh[col + j];
            }
            // reduce over the 16 tx lanes (two independent width-16 halves per warp)
            #pragma unroll
            for (int off = 8; off > 0; off >>= 1)
                pl += __shfl_down_sync(0xffffffffu, pl, off, 16);
            if (tx == 0) logits[b] = pl;
        }
        __syncthreads();
    }

    // softmax over b (256 entries, 256 threads)
    float lv = logits[tid];
    red[tid] = lv;
    __syncthreads();
    #pragma unroll
    for (int s = 128; s > 0; s >>= 1) {
        if (tid < s) red[tid] = fmaxf(red[tid], red[tid + s]);
        __syncthreads();
    }
    float mx = red[0];
    __syncthreads();
    float ev = expf(lv - mx);
    red[tid] = ev;
    __syncthreads();
    #pragma unroll
    for (int s = 128; s > 0; s >>= 1) {
        if (tid < s) red[tid] += red[tid + s];
        __syncthreads();
    }
    float inv = 1.0f / red[0];
    __syncthreads();
    logits[tid] = ev * inv;
    __syncthreads();

    // out[n,a,:] = x[n,a,:] + att @ v[n]   (split the 256-long b-sum over 2 halves)
    {
        int d = tid & 127, h = tid >> 7;
        const float* vb = &g_v[(n*PP + h*128)*CC + d];
        float s0 = 0.f, s1 = 0.f;
        #pragma unroll 4
        for (int b = 0; b < 128; b += 2) {
            s0 += logits[h*128 + b    ] * vb[(b    )*CC];
            s1 += logits[h*128 + b + 1] * vb[(b + 1)*CC];
        }
        red[tid] = s0 + s1;
    }
    __syncthreads();
    if (tid < CC) {
        int o = (n*PP + a)*CC + tid;
        out[o] = x[o] + red[tid] + red[tid + 128];
    }
}

// ---------------------------------------------------------------------------
extern "C" void kernel_launch(void* const* d_in, const int* in_sizes, int n_in,
                              void* d_out, int out_size) {
    const float* x   = (const float*)d_in[0];
    const float* pos = (const float*)d_in[1];
    const float* Wq  = (const float*)d_in[2];
    const float* Wk  = (const float*)d_in[3];
    const float* Wv  = (const float*)d_in[4];
    const float* W1  = (const float*)d_in[5];
    const float* b1  = (const float*)d_in[6];
    const float* W2  = (const float*)d_in[7];
    // d_in[8] = b2: constant shift, cancelled by softmax — unused
    const float* Wp1 = (const float*)d_in[9];
    const float* bp1 = (const float*)d_in[10];
    const float* Wp2 = (const float*)d_in[11];
    const float* bp2 = (const float*)d_in[12];
    float* out = (float*)d_out;

    const int smem_proj = (CC*CC + 64*US) * 4;                       // 99328
    const int smem_main = (CC*CC + 64*US + 6*CC + 2*PP) * 4;         // 104448
    cudaFuncSetAttribute(proj_kernel, cudaFuncAttributeMaxDynamicSharedMemorySize, smem_proj);
    cudaFuncSetAttribute(main_kernel, cudaFuncAttributeMaxDynamicSharedMemorySize, smem_main);

    prep_weights<<<3, 256>>>(Wq, Wk, Wp2, W1, b1, bp2);
    proj_kernel<<<dim3(NB*PP/64, 3), 256, smem_proj>>>(x, Wv);
    main_kernel<<<NB*PP, 256, smem_main>>>(x, pos, W2, Wp1, bp1, out);
}